// round 12
// baseline (speedup 1.0000x reference)
#include <cuda_runtime.h>
#include <cuda_fp16.h>

#define B_DIM 2048
#define IN_DIM 8192
#define O_DIM 4096
#define K_DIM 64

// 32 MB transposed fp16 copy of x: xth[i][b] (b contiguous, L2-resident)
__device__ __half g_xth[(size_t)IN_DIM * B_DIM];

// Sorted+packed refs, laid out in gather access order:
// g_pk2[chunk*16384 + rank*256 + o_local] = (idx<<16) | fp16(w)
// where chunk = o>>8, o_local = o&255, rank = position of this ref in o's
// idx-ascending order. 1 MB.
__device__ unsigned int g_pk2[O_DIM * K_DIM];

// ---------------------------------------------------------------------------
// Kernel 0: per-o sort of the 64 refs by idx (rank-by-counting, warp per o),
// scattered into the chunk/rank/o_local layout the gather streams.
// ---------------------------------------------------------------------------
__global__ __launch_bounds__(256) void sort_pack_kernel(const int* __restrict__ indices,
                                                        const float* __restrict__ weight) {
    __shared__ int sidx[8][64];
    const int warp = threadIdx.x >> 5;
    const int lane = threadIdx.x & 31;
    const int o = blockIdx.x * 8 + warp;

    const int i0 = indices[o * K_DIM + lane];
    const int i1 = indices[o * K_DIM + lane + 32];
    sidx[warp][lane] = i0;
    sidx[warp][lane + 32] = i1;
    __syncwarp();

    int r0 = 0, r1 = 0;
#pragma unroll
    for (int j = 0; j < 64; j++) {
        const int vj = sidx[warp][j];
        r0 += (vj < i0) || (vj == i0 && j < lane);
        r1 += (vj < i1) || (vj == i1 && j < (lane + 32));
    }

    const unsigned int h0 = __half_as_ushort(__float2half(weight[o * K_DIM + lane]));
    const unsigned int h1 = __half_as_ushort(__float2half(weight[o * K_DIM + lane + 32]));
    const int chunk = o >> 8;
    const int ol = o & 255;
    g_pk2[chunk * (64 * 256) + r0 * 256 + ol] = ((unsigned int)i0 << 16) | h0;
    g_pk2[chunk * (64 * 256) + r1 * 256 + ol] = ((unsigned int)i1 << 16) | h1;
}

// ---------------------------------------------------------------------------
// Kernel 1: transpose+convert x[B, IN] f32 -> g_xth[IN, B] f16 (R11, proven).
// ---------------------------------------------------------------------------
#define TPITCH 76

__global__ __launch_bounds__(256) void transpose_kernel(const float* __restrict__ x) {
    __shared__ __half2 st2[32][TPITCH];
    const int i0 = blockIdx.x * 64;
    const int b0 = blockIdx.y * 64;
    const int t = threadIdx.x;

    {
        const int r = t >> 2;
        const int c = t & 3;
        const float4* __restrict__ xr = (const float4*)(x + (size_t)(b0 + r) * IN_DIM + i0);
#pragma unroll
        for (int j = 0; j < 4; j++) {
            const float4 f = xr[c + 4 * j];
            const int i2 = 2 * c + 8 * j;
            st2[i2 + 0][r] = __floats2half2_rn(f.x, f.y);
            st2[i2 + 1][r] = __floats2half2_rn(f.z, f.w);
        }
    }
    __syncthreads();
    {
        const int p2 = t >> 4;
        const int m = t & 15;
        const int bb = 4 * m;
#pragma unroll
        for (int pp = 0; pp < 2; pp++) {
            const int p = 2 * p2 + pp;
            const uint4 u = *(const uint4*)&st2[p][bb];
            unsigned int lo0 = __byte_perm(u.x, u.y, 0x5410);
            unsigned int lo1 = __byte_perm(u.z, u.w, 0x5410);
            unsigned int hi0 = __byte_perm(u.x, u.y, 0x7632);
            unsigned int hi1 = __byte_perm(u.z, u.w, 0x7632);
            __half* __restrict__ row0 = g_xth + (size_t)(i0 + 2 * p + 0) * B_DIM + b0 + bb;
            __half* __restrict__ row1 = g_xth + (size_t)(i0 + 2 * p + 1) * B_DIM + b0 + bb;
            *(uint2*)row0 = make_uint2(lo0, lo1);
            *(uint2*)row1 = make_uint2(hi0, hi1);
        }
    }
}

// ---------------------------------------------------------------------------
// Kernel 2: windowed gather.
// CTA = (64-b slice, 256-o chunk); grid (32, 16) = 512 CTAs, 256 threads.
// 8-lane group g owns o's [C0+8g, C0+8g+8), each lane 8 consecutive b's.
// Per (k, oo): group reads one 128B line of xt (1 wavefront) for its o's
// k-th SORTED ref -> all concurrent o's sweep rows in lockstep -> row reuse
// across o's served by L1 instead of L2.
// Refs staged per 4-k block from g_pk2 (coalesced); acc[8][8] fp32 static.
// Epilogue: register transpose -> 32B full-sector stores out[b][o..o+7].
// ---------------------------------------------------------------------------
#define GT 256

__global__ __launch_bounds__(GT) void gather_kernel(const float* __restrict__ bias,
                                                    float* __restrict__ out) {
    __shared__ unsigned int s_pk[4 * 256];  // 4 KB staging (4 k-steps x 256 o's)

    const int tid = threadIdx.x;
    const int g = tid >> 3;       // group 0..31
    const int l = tid & 7;        // lane-in-group
    const int slice = blockIdx.x; // b-slice: b in [64*slice, 64*slice+64)
    const int C0 = blockIdx.y * 256;
    const int sbase = slice * 8 + l;  // uint4 column within an xt row

    const uint4* __restrict__ xt8 = (const uint4*)g_xth;
    const unsigned int* __restrict__ pkc = g_pk2 + blockIdx.y * (64 * 256);

    float acc[8][8];
#pragma unroll
    for (int oo = 0; oo < 8; oo++)
#pragma unroll
        for (int q = 0; q < 8; q++) acc[oo][q] = 0.f;

    for (int kb = 0; kb < 16; kb++) {
        __syncthreads();  // protect prior block's s_pk reads
#pragma unroll
        for (int j = 0; j < 4; j++)
            s_pk[tid + j * 256] = pkc[kb * 1024 + tid + j * 256];
        __syncthreads();

#pragma unroll
        for (int kk = 0; kk < 4; kk++) {
#pragma unroll
            for (int oo = 0; oo < 8; oo++) {
                const unsigned int e = s_pk[kk * 256 + g * 8 + oo];  // LDS broadcast in group
                const float wv = __half2float(__ushort_as_half((unsigned short)(e & 0xFFFFu)));
                const uint4 v = xt8[(e >> 16) * 256 + sbase];  // group = one 128B line
                const __half2* h = (const __half2*)&v;
#pragma unroll
                for (int q = 0; q < 4; q++) {
                    const float2 f = __half22float2(h[q]);
                    acc[oo][2 * q + 0] += f.x * wv;
                    acc[oo][2 * q + 1] += f.y * wv;
                }
            }
        }
    }

    // Epilogue: bias + transpose to o-contiguous 32B stores.
    float bv[8];
    const int ob = C0 + g * 8;
#pragma unroll
    for (int oo = 0; oo < 8; oo++) bv[oo] = bias[ob + oo];

#pragma unroll
    for (int bb = 0; bb < 8; bb++) {
        const int b = slice * 64 + l * 8 + bb;
        float4 v0 = make_float4(acc[0][bb] + bv[0], acc[1][bb] + bv[1],
                                acc[2][bb] + bv[2], acc[3][bb] + bv[3]);
        float4 v1 = make_float4(acc[4][bb] + bv[4], acc[5][bb] + bv[5],
                                acc[6][bb] + bv[6], acc[7][bb] + bv[7]);
        float4* dst = (float4*)(out + (size_t)b * O_DIM + ob);
        dst[0] = v0;
        dst[1] = v1;
    }
}

// ---------------------------------------------------------------------------
// Launch
// ---------------------------------------------------------------------------
extern "C" void kernel_launch(void* const* d_in, const int* in_sizes, int n_in,
                              void* d_out, int out_size) {
    (void)in_sizes; (void)n_in; (void)out_size;
    const float* x = (const float*)d_in[0];
    const int* indices = (const int*)d_in[1];
    const float* weight = (const float*)d_in[2];
    const float* bias = (const float*)d_in[3];
    float* out = (float*)d_out;

    sort_pack_kernel<<<O_DIM / 8, 256>>>(indices, weight);

    dim3 tg(IN_DIM / 64, B_DIM / 64);  // (128, 32)
    transpose_kernel<<<tg, 256>>>(x);

    dim3 gg(B_DIM / 64, O_DIM / 256);  // (32, 16)
    gather_kernel<<<gg, GT>>>(bias, out);
}

// round 13
// speedup vs baseline: 1.5133x; 1.5133x over previous
#include <cuda_runtime.h>
#include <cuda_fp16.h>

#define B_DIM 2048
#define IN_DIM 8192
#define O_DIM 4096
#define K_DIM 64

// 32 MB transposed fp16 copy of x: xth[i][b] (b contiguous, L2-resident)
__device__ __half g_xth[(size_t)IN_DIM * B_DIM];

// ---------------------------------------------------------------------------
// Kernel 1: transpose+convert x[B, IN] f32 -> g_xth[IN, B] f16.
// R11 version (measured ~12us, near the 96MB DRAM/LTS floor). Unchanged.
// ---------------------------------------------------------------------------
#define TPITCH 76

__global__ __launch_bounds__(256) void transpose_kernel(const float* __restrict__ x) {
    __shared__ __half2 st2[32][TPITCH];
    const int i0 = blockIdx.x * 64;
    const int b0 = blockIdx.y * 64;
    const int t = threadIdx.x;

    {
        const int r = t >> 2;
        const int c = t & 3;
        const float4* __restrict__ xr = (const float4*)(x + (size_t)(b0 + r) * IN_DIM + i0);
#pragma unroll
        for (int j = 0; j < 4; j++) {
            const float4 f = xr[c + 4 * j];
            const int i2 = 2 * c + 8 * j;
            st2[i2 + 0][r] = __floats2half2_rn(f.x, f.y);
            st2[i2 + 1][r] = __floats2half2_rn(f.z, f.w);
        }
    }
    __syncthreads();
    {
        const int p2 = t >> 4;
        const int m = t & 15;
        const int bb = 4 * m;
#pragma unroll
        for (int pp = 0; pp < 2; pp++) {
            const int p = 2 * p2 + pp;
            const uint4 u = *(const uint4*)&st2[p][bb];
            unsigned int lo0 = __byte_perm(u.x, u.y, 0x5410);
            unsigned int lo1 = __byte_perm(u.z, u.w, 0x5410);
            unsigned int hi0 = __byte_perm(u.x, u.y, 0x7632);
            unsigned int hi1 = __byte_perm(u.z, u.w, 0x7632);
            __half* __restrict__ row0 = g_xth + (size_t)(i0 + 2 * p + 0) * B_DIM + b0 + bb;
            __half* __restrict__ row1 = g_xth + (size_t)(i0 + 2 * p + 1) * B_DIM + b0 + bb;
            *(uint2*)row0 = make_uint2(lo0, lo1);
            *(uint2*)row1 = make_uint2(hi0, hi1);
        }
    }
}

// ---------------------------------------------------------------------------
// Kernel 2: gather + weighted reduce (fp16 xt, fp32 accumulate).
// R11 inner loop (proven at the L2 read-sector roof), re-chunked to probe
// wave-tail slack: OT 8->4 => grid (1,1024), 2KB smem, acc[4][8]=32 regs,
// launch_bounds(256,4) => 4 CTAs/SM, 592 resident, 1.73 fine-grained waves
// (vs R11's 3.46 coarse waves with a 46%-occupied tail).
// Thread owns 8 consecutive b (one uint4 of halves); 256 thr cover all B.
// ---------------------------------------------------------------------------
#define OT 4
#define NTHR 256

__global__ __launch_bounds__(NTHR, 4) void gather_kernel(const int* __restrict__ indices,
                                                         const float* __restrict__ weight,
                                                         const float* __restrict__ bias,
                                                         float* __restrict__ out) {
    __shared__ int2 s_iw[OT * K_DIM];  // 2 KB: {premultiplied row offset, w bits}

    const int tid = threadIdx.x;
    const int obase = blockIdx.y * OT;
    const int brow = tid * 8;  // first of this thread's 8 b's

    // Stage refs: exactly one int2 per thread (OT*K == NTHR)
    {
        int2 iw;
        iw.x = indices[(size_t)obase * K_DIM + tid] * (B_DIM / 8);
        iw.y = __float_as_int(weight[(size_t)obase * K_DIM + tid]);
        s_iw[tid] = iw;
    }
    __syncthreads();

    const uint4* __restrict__ xt8 = (const uint4*)g_xth;

    float acc[OT][8];
#pragma unroll
    for (int j = 0; j < OT; j++)
#pragma unroll
        for (int q = 0; q < 8; q++) acc[j][q] = 0.f;

#pragma unroll 2
    for (int k = 0; k < K_DIM; k++) {
#pragma unroll
        for (int j = 0; j < OT; j++) {
            const int2 iw = s_iw[j * K_DIM + k];  // one LDS.64
            const float w = __int_as_float(iw.y);
            const uint4 v = xt8[iw.x + tid];      // 8 halves, coalesced along b
            const __half2* h = (const __half2*)&v;
#pragma unroll
            for (int q = 0; q < 4; q++) {
                const float2 f = __half22float2(h[q]);
                acc[j][2 * q + 0] += f.x * w;
                acc[j][2 * q + 1] += f.y * w;
            }
        }
    }

    float bv[OT];
#pragma unroll
    for (int j = 0; j < OT; j++) bv[j] = bias[obase + j];

    // Full-width stores: out[b][obase..obase+3] as one STG.128 per b
#pragma unroll
    for (int bb = 0; bb < 8; bb++) {
        float4 v;
        v.x = acc[0][bb] + bv[0];
        v.y = acc[1][bb] + bv[1];
        v.z = acc[2][bb] + bv[2];
        v.w = acc[3][bb] + bv[3];
        *(float4*)(out + (size_t)(brow + bb) * O_DIM + obase) = v;
    }
}

// ---------------------------------------------------------------------------
// Launch
// ---------------------------------------------------------------------------
extern "C" void kernel_launch(void* const* d_in, const int* in_sizes, int n_in,
                              void* d_out, int out_size) {
    (void)in_sizes; (void)n_in; (void)out_size;
    const float* x = (const float*)d_in[0];
    const int* indices = (const int*)d_in[1];
    const float* weight = (const float*)d_in[2];
    const float* bias = (const float*)d_in[3];
    float* out = (float*)d_out;

    dim3 tg(IN_DIM / 64, B_DIM / 64);  // (128, 32)
    transpose_kernel<<<tg, 256>>>(x);

    dim3 gg(1, O_DIM / OT);  // (1, 1024)
    gather_kernel<<<gg, NTHR>>>(indices, weight, bias, out);
}